// round 1
// baseline (speedup 1.0000x reference)
#include <cuda_runtime.h>
#include <cuda_bf16.h>
#include <math.h>

#define TT 8
#define NN 50000
#define EE 800000
#define FF 128
#define HH 128

// ---------------- device scratch (no allocs allowed) ----------------
__device__ float g_agg[(size_t)NN * HH];
__device__ float g_bufA[(size_t)NN * HH];
__device__ float g_bufB[(size_t)NN * HH];
__device__ int   g_cnt[NN];
__device__ float g_inv[NN];
__device__ float g_pooled[TT * HH];

// ---------------- small utility kernels ----------------
__global__ void zero_f4_kernel(float4* __restrict__ p, int n4) {
    int i = blockIdx.x * blockDim.x + threadIdx.x;
    int stride = gridDim.x * blockDim.x;
    float4 z = make_float4(0.f, 0.f, 0.f, 0.f);
    for (; i < n4; i += stride) p[i] = z;
}

__global__ void deg_kernel(const int* __restrict__ dst, int* __restrict__ cnt, int E) {
    int e = blockIdx.x * blockDim.x + threadIdx.x;
    if (e < E) atomicAdd(&cnt[dst[e]], 1);
}

__global__ void inv_kernel(const int* __restrict__ cnt, float* __restrict__ inv, int n) {
    int i = blockIdx.x * blockDim.x + threadIdx.x;
    if (i < n) {
        int c = cnt[i];
        inv[i] = 1.0f / (float)(c > 0 ? c : 1);
    }
}

// ---------------- scatter: one warp per edge, red.global.add.v4.f32 ----------------
__device__ __forceinline__ void red_add4(float* addr, float4 v) {
    asm volatile("red.global.add.v4.f32 [%0], {%1, %2, %3, %4};"
                 :: "l"(addr), "f"(v.x), "f"(v.y), "f"(v.z), "f"(v.w)
                 : "memory");
}

__global__ void scatter_kernel(const float* __restrict__ x,
                               const int* __restrict__ src,
                               const int* __restrict__ dst,
                               float* __restrict__ agg, int E) {
    int w = (blockIdx.x * blockDim.x + threadIdx.x) >> 5;
    int lane = threadIdx.x & 31;
    if (w >= E) return;
    int s = src[w];
    int d = dst[w];
    const float4* row = (const float4*)(x + (size_t)s * HH);
    float4 v = row[lane];
    red_add4(agg + (size_t)d * HH + lane * 4, v);
}

// ---------------- fused SAGE GEMM: out = relu(agg*inv @ Wl + x @ Wr + b) ------------
// C[N x 128] = A[N x 256] @ W[256 x 128], A = [agg*inv | x], W = [Wl ; Wr]
// Block tile 128x128, K=256, BK=16, 256 threads, 8x8 per-thread micro-tile.
template<bool POOL>
__global__ __launch_bounds__(256)
void sage_gemm_kernel(const float* __restrict__ A1,   // agg
                      const float* __restrict__ inv,
                      const float* __restrict__ A2,   // x
                      const float* __restrict__ Wl,
                      const float* __restrict__ Wr,
                      const float* __restrict__ bias,
                      float* __restrict__ out,        // !POOL: N*H ; POOL: pooled_t[128] (atomic)
                      int n) {
    __shared__ float As[16][128];
    __shared__ float Bs[16][128];

    int tid = threadIdx.x;
    int tx = tid & 15;        // col group
    int ty = tid >> 4;        // row group
    int row0 = blockIdx.x * 128;

    float acc[8][8];
#pragma unroll
    for (int r = 0; r < 8; r++)
#pragma unroll
        for (int c = 0; c < 8; c++) acc[r][c] = 0.f;

#pragma unroll 1
    for (int kt = 0; kt < 16; kt++) {
        int k0 = kt * 16;
        bool isAgg = (k0 < 128);
        const float* Asrc = isAgg ? A1 : A2;
        const float* Wsrc = isAgg ? Wl : Wr;
        int ksrc = isAgg ? k0 : (k0 - 128);

        // load A tile (128 rows x 16 k), transposed into As[k][i], scaled by inv for agg
#pragma unroll
        for (int it = 0; it < 2; it++) {
            int i = (tid >> 2) + it * 64;
            int kk = (tid & 3) * 4;
            int gi = row0 + i;
            float4 v = make_float4(0.f, 0.f, 0.f, 0.f);
            if (gi < n) {
                v = *(const float4*)&Asrc[(size_t)gi * 128 + ksrc + kk];
                if (isAgg) {
                    float s = inv[gi];
                    v.x *= s; v.y *= s; v.z *= s; v.w *= s;
                }
            }
            As[kk + 0][i] = v.x;
            As[kk + 1][i] = v.y;
            As[kk + 2][i] = v.z;
            As[kk + 3][i] = v.w;
        }
        // load B tile (16 k x 128 j)
#pragma unroll
        for (int it = 0; it < 2; it++) {
            int kk = (tid >> 5) + it * 8;
            int j = (tid & 31) * 4;
            *(float4*)&Bs[kk][j] = *(const float4*)&Wsrc[(size_t)(ksrc + kk) * 128 + j];
        }
        __syncthreads();

#pragma unroll
        for (int k = 0; k < 16; k++) {
            float a[8], b[8];
            *(float4*)&a[0] = *(const float4*)&As[k][ty * 8];
            *(float4*)&a[4] = *(const float4*)&As[k][ty * 8 + 4];
            *(float4*)&b[0] = *(const float4*)&Bs[k][tx * 8];
            *(float4*)&b[4] = *(const float4*)&Bs[k][tx * 8 + 4];
#pragma unroll
            for (int r = 0; r < 8; r++)
#pragma unroll
                for (int c = 0; c < 8; c++) acc[r][c] += a[r] * b[c];
        }
        __syncthreads();
    }

    float bv[8];
    *(float4*)&bv[0] = *(const float4*)&bias[tx * 8];
    *(float4*)&bv[4] = *(const float4*)&bias[tx * 8 + 4];

    if (!POOL) {
#pragma unroll
        for (int r = 0; r < 8; r++) {
            int gi = row0 + ty * 8 + r;
            if (gi < n) {
                float o[8];
#pragma unroll
                for (int c = 0; c < 8; c++) o[c] = fmaxf(acc[r][c] + bv[c], 0.f);
                *(float4*)&out[(size_t)gi * 128 + tx * 8]     = *(float4*)&o[0];
                *(float4*)&out[(size_t)gi * 128 + tx * 8 + 4] = *(float4*)&o[4];
            }
        }
    } else {
        // fused mean-pool contribution: column sums of relu output over valid rows
        float colsum[8];
#pragma unroll
        for (int c = 0; c < 8; c++) colsum[c] = 0.f;
#pragma unroll
        for (int r = 0; r < 8; r++) {
            int gi = row0 + ty * 8 + r;
            if (gi < n) {
#pragma unroll
                for (int c = 0; c < 8; c++)
                    colsum[c] += fmaxf(acc[r][c] + bv[c], 0.f);
            }
        }
        // reduce across the 16 ty groups via shared (reuse As: 16*128 floats)
        float* red = &As[0][0];
        *(float4*)&red[ty * 128 + tx * 8]     = *(float4*)&colsum[0];
        *(float4*)&red[ty * 128 + tx * 8 + 4] = *(float4*)&colsum[4];
        __syncthreads();
        if (ty == 0) {
#pragma unroll
            for (int c = 0; c < 8; c++) {
                float s = 0.f;
#pragma unroll
                for (int g = 0; g < 16; g++) s += red[g * 128 + tx * 8 + c];
                atomicAdd(&out[tx * 8 + c], s);
            }
        }
    }
}

// ---------------- head: attention (only last q row) + MLP + sigmoid ----------------
__global__ void head_kernel(const float* __restrict__ pooled,
                            const float* __restrict__ Wq, const float* __restrict__ bq,
                            const float* __restrict__ Wk, const float* __restrict__ bk,
                            const float* __restrict__ Wv, const float* __restrict__ bv,
                            const float* __restrict__ Wo, const float* __restrict__ bo,
                            const float* __restrict__ Wh1, const float* __restrict__ bh1,
                            const float* __restrict__ Wh2, const float* __restrict__ bh2,
                            float* __restrict__ out) {
    __shared__ float seq[TT][HH];
    __shared__ float kk_s[TT][HH];
    __shared__ float vv_s[TT][HH];
    __shared__ float qv[HH];
    __shared__ float sc[4][TT];
    __shared__ float ol[HH];
    __shared__ float zz[HH];
    __shared__ float h1s[64];

    int j = threadIdx.x;  // 0..127
    const float invN = 1.0f / (float)NN;

    for (int t = 0; t < TT; t++) seq[t][j] = pooled[t * HH + j] * invN;
    __syncthreads();

    // q (only last row), k, v projections
    {
        float aq = bq[j];
        for (int k = 0; k < HH; k++) aq += seq[TT - 1][k] * Wq[k * HH + j];
        qv[j] = aq;
        for (int t = 0; t < TT; t++) {
            float ak = bk[j], av = bv[j];
            for (int k = 0; k < HH; k++) {
                float s = seq[t][k];
                ak += s * Wk[k * HH + j];
                av += s * Wv[k * HH + j];
            }
            kk_s[t][j] = ak;
            vv_s[t][j] = av;
        }
    }
    __syncthreads();

    // scores for q row T-1, 4 heads x 8 keys
    if (j < 32) {
        int h = j >> 3, t = j & 7;
        float s = 0.f;
        for (int d = 0; d < 32; d++) s += qv[h * 32 + d] * kk_s[t][h * 32 + d];
        sc[h][t] = s * 0.17677669529663687f;  // 1/sqrt(32)
    }
    __syncthreads();
    if (j < 4) {
        float m = sc[j][0];
        for (int t = 1; t < TT; t++) m = fmaxf(m, sc[j][t]);
        float s = 0.f;
        for (int t = 0; t < TT; t++) { float e = expf(sc[j][t] - m); sc[j][t] = e; s += e; }
        float r = 1.0f / s;
        for (int t = 0; t < TT; t++) sc[j][t] *= r;
    }
    __syncthreads();

    // o (last row) = attn @ v
    {
        int h = j >> 5;
        float o = 0.f;
        for (int t = 0; t < TT; t++) o += sc[h][t] * vv_s[t][j];
        ol[j] = o;
    }
    __syncthreads();

    // z = o @ Wo + bo
    {
        float a = bo[j];
        for (int k = 0; k < HH; k++) a += ol[k] * Wo[k * HH + j];
        zz[j] = a;
    }
    __syncthreads();

    // h1 = relu(z @ Wh1 + bh1)   (128 -> 64)
    if (j < 64) {
        float a = bh1[j];
        for (int k = 0; k < HH; k++) a += zz[k] * Wh1[k * 64 + j];
        h1s[j] = fmaxf(a, 0.f);
    }
    __syncthreads();

    if (j == 0) {
        float a = bh2[0];
        for (int k = 0; k < 64; k++) a += h1s[k] * Wh2[k];
        out[0] = 1.0f / (1.0f + expf(-a));
    }
}

// ---------------- host ----------------
extern "C" void kernel_launch(void* const* d_in, const int* in_sizes, int n_in,
                              void* d_out, int out_size) {
    const float* xs  = (const float*)d_in[0];
    const int*   ei  = (const int*)d_in[1];
    const float* Wl1 = (const float*)d_in[2];
    const float* Wr1 = (const float*)d_in[3];
    const float* b1  = (const float*)d_in[4];
    const float* Wl2 = (const float*)d_in[5];
    const float* Wr2 = (const float*)d_in[6];
    const float* b2  = (const float*)d_in[7];
    const float* Wl3 = (const float*)d_in[8];
    const float* Wr3 = (const float*)d_in[9];
    const float* b3  = (const float*)d_in[10];
    const float* Wq  = (const float*)d_in[11];
    const float* bq  = (const float*)d_in[12];
    const float* Wk  = (const float*)d_in[13];
    const float* bk  = (const float*)d_in[14];
    const float* Wv  = (const float*)d_in[15];
    const float* bv  = (const float*)d_in[16];
    const float* Wo  = (const float*)d_in[17];
    const float* bo  = (const float*)d_in[18];
    const float* Wh1 = (const float*)d_in[19];
    const float* bh1 = (const float*)d_in[20];
    const float* Wh2 = (const float*)d_in[21];
    const float* bh2 = (const float*)d_in[22];
    float* out = (float*)d_out;

    float *agg, *bufA, *bufB, *inv, *pooled;
    int* cnt;
    cudaGetSymbolAddress((void**)&agg,    g_agg);
    cudaGetSymbolAddress((void**)&bufA,   g_bufA);
    cudaGetSymbolAddress((void**)&bufB,   g_bufB);
    cudaGetSymbolAddress((void**)&inv,    g_inv);
    cudaGetSymbolAddress((void**)&pooled, g_pooled);
    cudaGetSymbolAddress((void**)&cnt,    g_cnt);

    const int nh4 = NN * HH / 4;           // 1.6M float4
    const int scatterBlocks = (EE * 32 + 255) / 256;

    // zero pooled accumulator
    zero_f4_kernel<<<4, 256>>>((float4*)pooled, TT * HH / 4);

    for (int t = 0; t < TT; t++) {
        const float* x_t = xs + (size_t)t * NN * FF;
        const int* src_t = ei + (size_t)t * 2 * EE;
        const int* dst_t = src_t + EE;

        // degree + inverse (shared across the 3 layers)
        zero_f4_kernel<<<64, 256>>>((float4*)cnt, NN / 4);
        deg_kernel<<<(EE + 255) / 256, 256>>>(dst_t, cnt, EE);
        inv_kernel<<<(NN + 255) / 256, 256>>>(cnt, inv, NN);

        // ---- layer 1 ----
        zero_f4_kernel<<<2048, 256>>>((float4*)agg, nh4);
        scatter_kernel<<<scatterBlocks, 256>>>(x_t, src_t, dst_t, agg, EE);
        sage_gemm_kernel<false><<<(NN + 127) / 128, 256>>>(agg, inv, x_t, Wl1, Wr1, b1, bufA, NN);

        // ---- layer 2 ----
        zero_f4_kernel<<<2048, 256>>>((float4*)agg, nh4);
        scatter_kernel<<<scatterBlocks, 256>>>(bufA, src_t, dst_t, agg, EE);
        sage_gemm_kernel<false><<<(NN + 127) / 128, 256>>>(agg, inv, bufA, Wl2, Wr2, b2, bufB, NN);

        // ---- layer 3 (output only feeds the mean-pool) ----
        zero_f4_kernel<<<2048, 256>>>((float4*)agg, nh4);
        scatter_kernel<<<scatterBlocks, 256>>>(bufB, src_t, dst_t, agg, EE);
        sage_gemm_kernel<true><<<(NN + 127) / 128, 256>>>(agg, inv, bufB, Wl3, Wr3, b3,
                                                          pooled + t * HH, NN);
    }

    head_kernel<<<1, 128>>>(pooled, Wq, bq, Wk, bk, Wv, bv, Wo, bo, Wh1, bh1, Wh2, bh2, out);
}

// round 2
// speedup vs baseline: 1.4100x; 1.4100x over previous
#include <cuda_runtime.h>
#include <cuda_bf16.h>
#include <math.h>

#define TT 8
#define NN 50000
#define EE 800000
#define FF 128
#define HH 128

// ---------------- device scratch (no allocs allowed) ----------------
__device__ float g_agg[(size_t)NN * HH];
__device__ float g_bufA[(size_t)NN * HH];
__device__ float g_bufB[(size_t)NN * HH];
__device__ int   g_cnt[NN];
__device__ int   g_off[NN + 1];
__device__ int   g_cur[NN];
__device__ int   g_csr[EE];
__device__ float g_inv[NN];
__device__ float g_pooled[TT * HH];

// ---------------- small utility kernels ----------------
__global__ void zero_i_kernel(int* __restrict__ p, int n) {
    int i = blockIdx.x * blockDim.x + threadIdx.x;
    if (i < n) p[i] = 0;
}

__global__ void zero_f4_kernel(float4* __restrict__ p, int n4) {
    int i = blockIdx.x * blockDim.x + threadIdx.x;
    if (i < n4) p[i] = make_float4(0.f, 0.f, 0.f, 0.f);
}

__global__ void deg_kernel(const int* __restrict__ dst, int* __restrict__ cnt, int E) {
    int e = blockIdx.x * blockDim.x + threadIdx.x;
    if (e < E) atomicAdd(&cnt[dst[e]], 1);
}

// single-block exclusive scan over cnt -> off/cur, plus inv = 1/max(cnt,1)
__global__ void scan_kernel(const int* __restrict__ cnt,
                            int* __restrict__ off, int* __restrict__ cur,
                            float* __restrict__ inv) {
    __shared__ int sh[1024];
    __shared__ int carry;
    if (threadIdx.x == 0) carry = 0;
    __syncthreads();
    for (int base = 0; base < NN; base += 1024) {
        int i = base + (int)threadIdx.x;
        int v = (i < NN) ? cnt[i] : 0;
        sh[threadIdx.x] = v;
        __syncthreads();
        // Hillis-Steele inclusive scan
        for (int ofs = 1; ofs < 1024; ofs <<= 1) {
            int t = (threadIdx.x >= ofs) ? sh[threadIdx.x - ofs] : 0;
            __syncthreads();
            sh[threadIdx.x] += t;
            __syncthreads();
        }
        int excl = carry + sh[threadIdx.x] - v;
        if (i < NN) {
            off[i] = excl;
            cur[i] = excl;
            inv[i] = 1.0f / (float)(v > 0 ? v : 1);
        }
        __syncthreads();
        if (threadIdx.x == 1023) carry += sh[1023];
        __syncthreads();
    }
    if (threadIdx.x == 0) off[NN] = carry;
}

__global__ void fill_kernel(const int* __restrict__ src, const int* __restrict__ dst,
                            int* __restrict__ cur, int* __restrict__ csr, int E) {
    int e = blockIdx.x * blockDim.x + threadIdx.x;
    if (e < E) {
        int d = dst[e];
        int p = atomicAdd(&cur[d], 1);
        csr[p] = src[e];
    }
}

// ---------------- pull-side aggregation: one warp per dst node --------------
// agg[node] = (sum over neighbors x[src]) * inv[node]
__global__ __launch_bounds__(256)
void agg_kernel(const float* __restrict__ x,
                const int* __restrict__ off,
                const int* __restrict__ csr,
                const float* __restrict__ inv,
                float* __restrict__ agg) {
    int node = (blockIdx.x * blockDim.x + threadIdx.x) >> 5;
    if (node >= NN) return;
    int lane = threadIdx.x & 31;
    int e = off[node];
    int e1 = off[node + 1];
    float4 acc = make_float4(0.f, 0.f, 0.f, 0.f);
    // 2-deep software pipeline for MLP
    for (; e + 1 < e1; e += 2) {
        int s0 = csr[e];
        int s1 = csr[e + 1];
        float4 v0 = ((const float4*)(x + (size_t)s0 * HH))[lane];
        float4 v1 = ((const float4*)(x + (size_t)s1 * HH))[lane];
        acc.x += v0.x + v1.x;
        acc.y += v0.y + v1.y;
        acc.z += v0.z + v1.z;
        acc.w += v0.w + v1.w;
    }
    if (e < e1) {
        int s0 = csr[e];
        float4 v0 = ((const float4*)(x + (size_t)s0 * HH))[lane];
        acc.x += v0.x; acc.y += v0.y; acc.z += v0.z; acc.w += v0.w;
    }
    float sc = inv[node];
    acc.x *= sc; acc.y *= sc; acc.z *= sc; acc.w *= sc;
    ((float4*)(agg + (size_t)node * HH))[lane] = acc;
}

// ---------------- fused SAGE GEMM: out = relu(aggS @ Wl + x @ Wr + b) ------------
// aggS is already degree-scaled. Block tile 128x128, K=256, BK=16, 256 threads.
template<bool POOL>
__global__ __launch_bounds__(256)
void sage_gemm_kernel(const float* __restrict__ A1,   // agg (scaled)
                      const float* __restrict__ A2,   // x
                      const float* __restrict__ Wl,
                      const float* __restrict__ Wr,
                      const float* __restrict__ bias,
                      float* __restrict__ out,        // !POOL: N*H ; POOL: pooled_t[128]
                      int n) {
    __shared__ float As[16][128];
    __shared__ float Bs[16][128];

    int tid = threadIdx.x;
    int tx = tid & 15;        // col group
    int ty = tid >> 4;        // row group
    int row0 = blockIdx.x * 128;

    float acc[8][8];
#pragma unroll
    for (int r = 0; r < 8; r++)
#pragma unroll
        for (int c = 0; c < 8; c++) acc[r][c] = 0.f;

#pragma unroll 1
    for (int kt = 0; kt < 16; kt++) {
        int k0 = kt * 16;
        bool isAgg = (k0 < 128);
        const float* Asrc = isAgg ? A1 : A2;
        const float* Wsrc = isAgg ? Wl : Wr;
        int ksrc = isAgg ? k0 : (k0 - 128);

#pragma unroll
        for (int it = 0; it < 2; it++) {
            int i = (tid >> 2) + it * 64;
            int kk = (tid & 3) * 4;
            int gi = row0 + i;
            float4 v = make_float4(0.f, 0.f, 0.f, 0.f);
            if (gi < n) v = *(const float4*)&Asrc[(size_t)gi * 128 + ksrc + kk];
            As[kk + 0][i] = v.x;
            As[kk + 1][i] = v.y;
            As[kk + 2][i] = v.z;
            As[kk + 3][i] = v.w;
        }
#pragma unroll
        for (int it = 0; it < 2; it++) {
            int kk = (tid >> 5) + it * 8;
            int j = (tid & 31) * 4;
            *(float4*)&Bs[kk][j] = *(const float4*)&Wsrc[(size_t)(ksrc + kk) * 128 + j];
        }
        __syncthreads();

#pragma unroll
        for (int k = 0; k < 16; k++) {
            float a[8], b[8];
            *(float4*)&a[0] = *(const float4*)&As[k][ty * 8];
            *(float4*)&a[4] = *(const float4*)&As[k][ty * 8 + 4];
            *(float4*)&b[0] = *(const float4*)&Bs[k][tx * 8];
            *(float4*)&b[4] = *(const float4*)&Bs[k][tx * 8 + 4];
#pragma unroll
            for (int r = 0; r < 8; r++)
#pragma unroll
                for (int c = 0; c < 8; c++) acc[r][c] += a[r] * b[c];
        }
        __syncthreads();
    }

    float bv[8];
    *(float4*)&bv[0] = *(const float4*)&bias[tx * 8];
    *(float4*)&bv[4] = *(const float4*)&bias[tx * 8 + 4];

    if (!POOL) {
#pragma unroll
        for (int r = 0; r < 8; r++) {
            int gi = row0 + ty * 8 + r;
            if (gi < n) {
                float o[8];
#pragma unroll
                for (int c = 0; c < 8; c++) o[c] = fmaxf(acc[r][c] + bv[c], 0.f);
                *(float4*)&out[(size_t)gi * 128 + tx * 8]     = *(float4*)&o[0];
                *(float4*)&out[(size_t)gi * 128 + tx * 8 + 4] = *(float4*)&o[4];
            }
        }
    } else {
        float colsum[8];
#pragma unroll
        for (int c = 0; c < 8; c++) colsum[c] = 0.f;
#pragma unroll
        for (int r = 0; r < 8; r++) {
            int gi = row0 + ty * 8 + r;
            if (gi < n) {
#pragma unroll
                for (int c = 0; c < 8; c++)
                    colsum[c] += fmaxf(acc[r][c] + bv[c], 0.f);
            }
        }
        float* red = &As[0][0];
        *(float4*)&red[ty * 128 + tx * 8]     = *(float4*)&colsum[0];
        *(float4*)&red[ty * 128 + tx * 8 + 4] = *(float4*)&colsum[4];
        __syncthreads();
        if (ty == 0) {
#pragma unroll
            for (int c = 0; c < 8; c++) {
                float s = 0.f;
#pragma unroll
                for (int g = 0; g < 16; g++) s += red[g * 128 + tx * 8 + c];
                atomicAdd(&out[tx * 8 + c], s);
            }
        }
    }
}

// ---------------- head: attention (only last q row) + MLP + sigmoid ----------------
__global__ void head_kernel(const float* __restrict__ pooled,
                            const float* __restrict__ Wq, const float* __restrict__ bq,
                            const float* __restrict__ Wk, const float* __restrict__ bk,
                            const float* __restrict__ Wv, const float* __restrict__ bv,
                            const float* __restrict__ Wo, const float* __restrict__ bo,
                            const float* __restrict__ Wh1, const float* __restrict__ bh1,
                            const float* __restrict__ Wh2, const float* __restrict__ bh2,
                            float* __restrict__ out) {
    __shared__ float seq[TT][HH];
    __shared__ float kk_s[TT][HH];
    __shared__ float vv_s[TT][HH];
    __shared__ float qv[HH];
    __shared__ float sc[4][TT];
    __shared__ float ol[HH];
    __shared__ float zz[HH];
    __shared__ float h1s[64];

    int j = threadIdx.x;  // 0..127
    const float invN = 1.0f / (float)NN;

    for (int t = 0; t < TT; t++) seq[t][j] = pooled[t * HH + j] * invN;
    __syncthreads();

    {
        float aq = bq[j];
        for (int k = 0; k < HH; k++) aq += seq[TT - 1][k] * Wq[k * HH + j];
        qv[j] = aq;
        for (int t = 0; t < TT; t++) {
            float ak = bk[j], av = bv[j];
            for (int k = 0; k < HH; k++) {
                float s = seq[t][k];
                ak += s * Wk[k * HH + j];
                av += s * Wv[k * HH + j];
            }
            kk_s[t][j] = ak;
            vv_s[t][j] = av;
        }
    }
    __syncthreads();

    if (j < 32) {
        int h = j >> 3, t = j & 7;
        float s = 0.f;
        for (int d = 0; d < 32; d++) s += qv[h * 32 + d] * kk_s[t][h * 32 + d];
        sc[h][t] = s * 0.17677669529663687f;  // 1/sqrt(32)
    }
    __syncthreads();
    if (j < 4) {
        float m = sc[j][0];
        for (int t = 1; t < TT; t++) m = fmaxf(m, sc[j][t]);
        float s = 0.f;
        for (int t = 0; t < TT; t++) { float e = expf(sc[j][t] - m); sc[j][t] = e; s += e; }
        float r = 1.0f / s;
        for (int t = 0; t < TT; t++) sc[j][t] *= r;
    }
    __syncthreads();

    {
        int h = j >> 5;
        float o = 0.f;
        for (int t = 0; t < TT; t++) o += sc[h][t] * vv_s[t][j];
        ol[j] = o;
    }
    __syncthreads();

    {
        float a = bo[j];
        for (int k = 0; k < HH; k++) a += ol[k] * Wo[k * HH + j];
        zz[j] = a;
    }
    __syncthreads();

    if (j < 64) {
        float a = bh1[j];
        for (int k = 0; k < HH; k++) a += zz[k] * Wh1[k * 64 + j];
        h1s[j] = fmaxf(a, 0.f);
    }
    __syncthreads();

    if (j == 0) {
        float a = bh2[0];
        for (int k = 0; k < 64; k++) a += h1s[k] * Wh2[k];
        out[0] = 1.0f / (1.0f + expf(-a));
    }
}

// ---------------- host ----------------
extern "C" void kernel_launch(void* const* d_in, const int* in_sizes, int n_in,
                              void* d_out, int out_size) {
    const float* xs  = (const float*)d_in[0];
    const int*   ei  = (const int*)d_in[1];
    const float* Wl1 = (const float*)d_in[2];
    const float* Wr1 = (const float*)d_in[3];
    const float* b1  = (const float*)d_in[4];
    const float* Wl2 = (const float*)d_in[5];
    const float* Wr2 = (const float*)d_in[6];
    const float* b2  = (const float*)d_in[7];
    const float* Wl3 = (const float*)d_in[8];
    const float* Wr3 = (const float*)d_in[9];
    const float* b3  = (const float*)d_in[10];
    const float* Wq  = (const float*)d_in[11];
    const float* bq  = (const float*)d_in[12];
    const float* Wk  = (const float*)d_in[13];
    const float* bk  = (const float*)d_in[14];
    const float* Wv  = (const float*)d_in[15];
    const float* bv  = (const float*)d_in[16];
    const float* Wo  = (const float*)d_in[17];
    const float* bo  = (const float*)d_in[18];
    const float* Wh1 = (const float*)d_in[19];
    const float* bh1 = (const float*)d_in[20];
    const float* Wh2 = (const float*)d_in[21];
    const float* bh2 = (const float*)d_in[22];
    float* out = (float*)d_out;

    float *agg, *bufA, *bufB, *inv, *pooled;
    int *cnt, *off, *cur, *csr;
    cudaGetSymbolAddress((void**)&agg,    g_agg);
    cudaGetSymbolAddress((void**)&bufA,   g_bufA);
    cudaGetSymbolAddress((void**)&bufB,   g_bufB);
    cudaGetSymbolAddress((void**)&inv,    g_inv);
    cudaGetSymbolAddress((void**)&pooled, g_pooled);
    cudaGetSymbolAddress((void**)&cnt,    g_cnt);
    cudaGetSymbolAddress((void**)&off,    g_off);
    cudaGetSymbolAddress((void**)&cur,    g_cur);
    cudaGetSymbolAddress((void**)&csr,    g_csr);

    const int aggBlocks  = (NN * 32 + 255) / 256;
    const int gemmBlocks = (NN + 127) / 128;

    zero_f4_kernel<<<1, 256>>>((float4*)pooled, TT * HH / 4);

    for (int t = 0; t < TT; t++) {
        const float* x_t = xs + (size_t)t * NN * FF;
        const int* src_t = ei + (size_t)t * 2 * EE;
        const int* dst_t = src_t + EE;

        // ---- CSR build (shared across 3 layers) ----
        zero_i_kernel<<<(NN + 255) / 256, 256>>>(cnt, NN);
        deg_kernel<<<(EE + 255) / 256, 256>>>(dst_t, cnt, EE);
        scan_kernel<<<1, 1024>>>(cnt, off, cur, inv);
        fill_kernel<<<(EE + 255) / 256, 256>>>(src_t, dst_t, cur, csr, EE);

        // ---- layer 1 ----
        agg_kernel<<<aggBlocks, 256>>>(x_t, off, csr, inv, agg);
        sage_gemm_kernel<false><<<gemmBlocks, 256>>>(agg, x_t, Wl1, Wr1, b1, bufA, NN);

        // ---- layer 2 ----
        agg_kernel<<<aggBlocks, 256>>>(bufA, off, csr, inv, agg);
        sage_gemm_kernel<false><<<gemmBlocks, 256>>>(agg, bufA, Wl2, Wr2, b2, bufB, NN);

        // ---- layer 3 (feeds mean-pool only) ----
        agg_kernel<<<aggBlocks, 256>>>(bufB, off, csr, inv, agg);
        sage_gemm_kernel<true><<<gemmBlocks, 256>>>(agg, bufB, Wl3, Wr3, b3,
                                                    pooled + t * HH, NN);
    }

    head_kernel<<<1, 128>>>(pooled, Wq, bq, Wk, bk, Wv, bv, Wo, bo, Wh1, bh1, Wh2, bh2, out);
}

// round 3
// speedup vs baseline: 1.6312x; 1.1569x over previous
#include <cuda_runtime.h>
#include <cuda_bf16.h>
#include <math.h>

#define TT 8
#define NN 50000
#define EE 800000
#define FF 128
#define HH 128
#define SCAN_BLOCKS ((NN + 255) / 256)   // 196

// ---------------- device scratch (no allocs allowed) ----------------
__device__ float g_agg[(size_t)NN * HH];
__device__ float g_bufA[(size_t)NN * HH];
__device__ float g_bufB[(size_t)NN * HH];
__device__ int   g_cnt[NN];
__device__ int   g_off[NN + 1];
__device__ int   g_cur[NN];
__device__ int   g_csr[EE];
__device__ int   g_bsum[SCAN_BLOCKS];
__device__ int   g_bbase[SCAN_BLOCKS];
__device__ float g_inv[NN];
__device__ float g_pooled[TT * HH];

// ---------------- packed f32x2 helpers ----------------
__device__ __forceinline__ unsigned long long pack_dup(float a) {
    unsigned long long r;
    unsigned int au = __float_as_uint(a);
    asm("mov.b64 %0, {%1, %1};" : "=l"(r) : "r"(au));
    return r;
}
__device__ __forceinline__ void ffma2(unsigned long long& acc, unsigned long long a,
                                      unsigned long long b) {
    asm("fma.rn.f32x2 %0, %1, %2, %3;" : "=l"(acc) : "l"(a), "l"(b), "l"(acc));
}
__device__ __forceinline__ void unpack2(unsigned long long v, float& lo, float& hi) {
    unsigned int l, h;
    asm("mov.b64 {%0, %1}, %2;" : "=r"(l), "=r"(h) : "l"(v));
    lo = __uint_as_float(l);
    hi = __uint_as_float(h);
}

// ---------------- small utility kernels ----------------
__global__ void zero_i_kernel(int* __restrict__ p, int n) {
    int i = blockIdx.x * blockDim.x + threadIdx.x;
    if (i < n) p[i] = 0;
}

__global__ void zero_f4_kernel(float4* __restrict__ p, int n4) {
    int i = blockIdx.x * blockDim.x + threadIdx.x;
    if (i < n4) p[i] = make_float4(0.f, 0.f, 0.f, 0.f);
}

__global__ void deg_kernel(const int* __restrict__ dst, int* __restrict__ cnt, int E) {
    int e = blockIdx.x * blockDim.x + threadIdx.x;
    if (e < E) atomicAdd(&cnt[dst[e]], 1);
}

// ---------------- 3-stage scan over cnt ----------------
// stage 1: per-256-block sums
__global__ void scan_reduce_kernel(const int* __restrict__ cnt, int* __restrict__ bsum) {
    __shared__ int wsum[8];
    int i = blockIdx.x * 256 + threadIdx.x;
    int v = (i < NN) ? cnt[i] : 0;
    int lane = threadIdx.x & 31;
    int wid = threadIdx.x >> 5;
    int s = v;
#pragma unroll
    for (int o = 16; o > 0; o >>= 1) s += __shfl_down_sync(0xffffffffu, s, o);
    if (lane == 0) wsum[wid] = s;
    __syncthreads();
    if (threadIdx.x == 0) {
        int t = 0;
#pragma unroll
        for (int w = 0; w < 8; w++) t += wsum[w];
        bsum[blockIdx.x] = t;
    }
}

// stage 2: scan SCAN_BLOCKS partials in one block -> exclusive bases + total
__global__ void scan_top_kernel(const int* __restrict__ bsum, int* __restrict__ bbase,
                                int* __restrict__ off_last) {
    __shared__ int wsum[8];
    int tid = threadIdx.x;                 // 256 threads
    int v = (tid < SCAN_BLOCKS) ? bsum[tid] : 0;
    int lane = tid & 31;
    int wid = tid >> 5;
    int s = v;
#pragma unroll
    for (int o = 1; o < 32; o <<= 1) {
        int t = __shfl_up_sync(0xffffffffu, s, o);
        if (lane >= o) s += t;
    }
    if (lane == 31) wsum[wid] = s;
    __syncthreads();
    if (wid == 0) {
        int ws = (lane < 8) ? wsum[lane] : 0;
#pragma unroll
        for (int o = 1; o < 8; o <<= 1) {
            int t = __shfl_up_sync(0xffffffffu, ws, o);
            if (lane >= o) ws += t;
        }
        if (lane < 8) wsum[lane] = ws;
    }
    __syncthreads();
    int incl = s + (wid > 0 ? wsum[wid - 1] : 0);
    if (tid < SCAN_BLOCKS) bbase[tid] = incl - v;
    if (tid == 255) off_last[0] = incl;    // total over all (padded zeros don't change it)
}

// stage 3: local exclusive scan + base -> off/cur/inv
__global__ void scan_final_kernel(const int* __restrict__ cnt, const int* __restrict__ bbase,
                                  int* __restrict__ off, int* __restrict__ cur,
                                  float* __restrict__ inv) {
    __shared__ int wsum[8];
    int i = blockIdx.x * 256 + threadIdx.x;
    int v = (i < NN) ? cnt[i] : 0;
    int lane = threadIdx.x & 31;
    int wid = threadIdx.x >> 5;
    int s = v;
#pragma unroll
    for (int o = 1; o < 32; o <<= 1) {
        int t = __shfl_up_sync(0xffffffffu, s, o);
        if (lane >= o) s += t;
    }
    if (lane == 31) wsum[wid] = s;
    __syncthreads();
    if (wid == 0) {
        int ws = (lane < 8) ? wsum[lane] : 0;
#pragma unroll
        for (int o = 1; o < 8; o <<= 1) {
            int t = __shfl_up_sync(0xffffffffu, ws, o);
            if (lane >= o) ws += t;
        }
        if (lane < 8) wsum[lane] = ws;
    }
    __syncthreads();
    int excl = s - v + (wid > 0 ? wsum[wid - 1] : 0) + bbase[blockIdx.x];
    if (i < NN) {
        off[i] = excl;
        cur[i] = excl;
        inv[i] = 1.0f / (float)(v > 0 ? v : 1);
    }
}

__global__ void fill_kernel(const int* __restrict__ src, const int* __restrict__ dst,
                            int* __restrict__ cur, int* __restrict__ csr, int E) {
    int e = blockIdx.x * blockDim.x + threadIdx.x;
    if (e < E) {
        int d = dst[e];
        int p = atomicAdd(&cur[d], 1);
        csr[p] = src[e];
    }
}

// ---------------- pull-side aggregation: one warp per dst node --------------
__global__ __launch_bounds__(256)
void agg_kernel(const float* __restrict__ x,
                const int* __restrict__ off,
                const int* __restrict__ csr,
                const float* __restrict__ inv,
                float* __restrict__ agg) {
    int node = (blockIdx.x * blockDim.x + threadIdx.x) >> 5;
    if (node >= NN) return;
    int lane = threadIdx.x & 31;
    int e = off[node];
    int e1 = off[node + 1];
    float4 acc = make_float4(0.f, 0.f, 0.f, 0.f);
    for (; e + 1 < e1; e += 2) {
        int s0 = csr[e];
        int s1 = csr[e + 1];
        float4 v0 = ((const float4*)(x + (size_t)s0 * HH))[lane];
        float4 v1 = ((const float4*)(x + (size_t)s1 * HH))[lane];
        acc.x += v0.x + v1.x;
        acc.y += v0.y + v1.y;
        acc.z += v0.z + v1.z;
        acc.w += v0.w + v1.w;
    }
    if (e < e1) {
        int s0 = csr[e];
        float4 v0 = ((const float4*)(x + (size_t)s0 * HH))[lane];
        acc.x += v0.x; acc.y += v0.y; acc.z += v0.z; acc.w += v0.w;
    }
    float sc = inv[node];
    acc.x *= sc; acc.y *= sc; acc.z *= sc; acc.w *= sc;
    ((float4*)(agg + (size_t)node * HH))[lane] = acc;
}

// ---------------- fused SAGE GEMM with packed f32x2 FMA ----------------
// out = relu(aggS @ Wl + x @ Wr + b); block tile 128x128, K=256, BK=16, 256 thr.
template<bool POOL>
__global__ __launch_bounds__(256)
void sage_gemm_kernel(const float* __restrict__ A1,   // agg (scaled)
                      const float* __restrict__ A2,   // x
                      const float* __restrict__ Wl,
                      const float* __restrict__ Wr,
                      const float* __restrict__ bias,
                      float* __restrict__ out,
                      int n) {
    __shared__ float As[16][128];
    __shared__ float Bs[16][128];

    int tid = threadIdx.x;
    int tx = tid & 15;        // col group (8 cols = 4 f32x2)
    int ty = tid >> 4;        // row group (8 rows)
    int row0 = blockIdx.x * 128;

    unsigned long long acc2[8][4];
#pragma unroll
    for (int r = 0; r < 8; r++)
#pragma unroll
        for (int c = 0; c < 4; c++) acc2[r][c] = 0ull;

#pragma unroll 1
    for (int kt = 0; kt < 16; kt++) {
        int k0 = kt * 16;
        bool isAgg = (k0 < 128);
        const float* Asrc = isAgg ? A1 : A2;
        const float* Wsrc = isAgg ? Wl : Wr;
        int ksrc = isAgg ? k0 : (k0 - 128);

#pragma unroll
        for (int it = 0; it < 2; it++) {
            int i = (tid >> 2) + it * 64;
            int kk = (tid & 3) * 4;
            int gi = row0 + i;
            float4 v = make_float4(0.f, 0.f, 0.f, 0.f);
            if (gi < n) v = *(const float4*)&Asrc[(size_t)gi * 128 + ksrc + kk];
            As[kk + 0][i] = v.x;
            As[kk + 1][i] = v.y;
            As[kk + 2][i] = v.z;
            As[kk + 3][i] = v.w;
        }
#pragma unroll
        for (int it = 0; it < 2; it++) {
            int kk = (tid >> 5) + it * 8;
            int j = (tid & 31) * 4;
            *(float4*)&Bs[kk][j] = *(const float4*)&Wsrc[(size_t)(ksrc + kk) * 128 + j];
        }
        __syncthreads();

#pragma unroll
        for (int k = 0; k < 16; k++) {
            float a[8];
            *(float4*)&a[0] = *(const float4*)&As[k][ty * 8];
            *(float4*)&a[4] = *(const float4*)&As[k][ty * 8 + 4];
            unsigned long long b2[4];
            const unsigned long long* bp = (const unsigned long long*)&Bs[k][tx * 8];
            b2[0] = bp[0]; b2[1] = bp[1]; b2[2] = bp[2]; b2[3] = bp[3];
#pragma unroll
            for (int r = 0; r < 8; r++) {
                unsigned long long aa = pack_dup(a[r]);
                ffma2(acc2[r][0], aa, b2[0]);
                ffma2(acc2[r][1], aa, b2[1]);
                ffma2(acc2[r][2], aa, b2[2]);
                ffma2(acc2[r][3], aa, b2[3]);
            }
        }
        __syncthreads();
    }

    float bv[8];
    *(float4*)&bv[0] = *(const float4*)&bias[tx * 8];
    *(float4*)&bv[4] = *(const float4*)&bias[tx * 8 + 4];

    if (!POOL) {
#pragma unroll
        for (int r = 0; r < 8; r++) {
            int gi = row0 + ty * 8 + r;
            if (gi < n) {
                float o[8];
#pragma unroll
                for (int c = 0; c < 4; c++) {
                    float lo, hi;
                    unpack2(acc2[r][c], lo, hi);
                    o[2 * c]     = fmaxf(lo + bv[2 * c], 0.f);
                    o[2 * c + 1] = fmaxf(hi + bv[2 * c + 1], 0.f);
                }
                *(float4*)&out[(size_t)gi * 128 + tx * 8]     = *(float4*)&o[0];
                *(float4*)&out[(size_t)gi * 128 + tx * 8 + 4] = *(float4*)&o[4];
            }
        }
    } else {
        float colsum[8];
#pragma unroll
        for (int c = 0; c < 8; c++) colsum[c] = 0.f;
#pragma unroll
        for (int r = 0; r < 8; r++) {
            int gi = row0 + ty * 8 + r;
            if (gi < n) {
#pragma unroll
                for (int c = 0; c < 4; c++) {
                    float lo, hi;
                    unpack2(acc2[r][c], lo, hi);
                    colsum[2 * c]     += fmaxf(lo + bv[2 * c], 0.f);
                    colsum[2 * c + 1] += fmaxf(hi + bv[2 * c + 1], 0.f);
                }
            }
        }
        float* red = &As[0][0];
        *(float4*)&red[ty * 128 + tx * 8]     = *(float4*)&colsum[0];
        *(float4*)&red[ty * 128 + tx * 8 + 4] = *(float4*)&colsum[4];
        __syncthreads();
        if (ty == 0) {
#pragma unroll
            for (int c = 0; c < 8; c++) {
                float s = 0.f;
#pragma unroll
                for (int g = 0; g < 16; g++) s += red[g * 128 + tx * 8 + c];
                atomicAdd(&out[tx * 8 + c], s);
            }
        }
    }
}

// ---------------- head: attention (only last q row) + MLP + sigmoid ----------------
__global__ void head_kernel(const float* __restrict__ pooled,
                            const float* __restrict__ Wq, const float* __restrict__ bq,
                            const float* __restrict__ Wk, const float* __restrict__ bk,
                            const float* __restrict__ Wv, const float* __restrict__ bv,
                            const float* __restrict__ Wo, const float* __restrict__ bo,
                            const float* __restrict__ Wh1, const float* __restrict__ bh1,
                            const float* __restrict__ Wh2, const float* __restrict__ bh2,
                            float* __restrict__ out) {
    __shared__ float seq[TT][HH];
    __shared__ float kk_s[TT][HH];
    __shared__ float vv_s[TT][HH];
    __shared__ float qv[HH];
    __shared__ float sc[4][TT];
    __shared__ float ol[HH];
    __shared__ float zz[HH];
    __shared__ float h1s[64];

    int j = threadIdx.x;  // 0..127
    const float invN = 1.0f / (float)NN;

    for (int t = 0; t < TT; t++) seq[t][j] = pooled[t * HH + j] * invN;
    __syncthreads();

    {
        float aq = bq[j];
        for (int k = 0; k < HH; k++) aq += seq[TT - 1][k] * Wq[k * HH + j];
        qv[j] = aq;
        for (int t = 0; t < TT; t++) {
            float ak = bk[j], av = bv[j];
            for (int k = 0; k < HH; k++) {
                float s = seq[t][k];
                ak += s * Wk[k * HH + j];
                av += s * Wv[k * HH + j];
            }
            kk_s[t][j] = ak;
            vv_s[t][j] = av;
        }
    }
    __syncthreads();

    if (j < 32) {
        int h = j >> 3, t = j & 7;
        float s = 0.f;
        for (int d = 0; d < 32; d++) s += qv[h * 32 + d] * kk_s[t][h * 32 + d];
        sc[h][t] = s * 0.17677669529663687f;
    }
    __syncthreads();
    if (j < 4) {
        float m = sc[j][0];
        for (int t = 1; t < TT; t++) m = fmaxf(m, sc[j][t]);
        float s = 0.f;
        for (int t = 0; t < TT; t++) { float e = expf(sc[j][t] - m); sc[j][t] = e; s += e; }
        float r = 1.0f / s;
        for (int t = 0; t < TT; t++) sc[j][t] *= r;
    }
    __syncthreads();

    {
        int h = j >> 5;
        float o = 0.f;
        for (int t = 0; t < TT; t++) o += sc[h][t] * vv_s[t][j];
        ol[j] = o;
    }
    __syncthreads();

    {
        float a = bo[j];
        for (int k = 0; k < HH; k++) a += ol[k] * Wo[k * HH + j];
        zz[j] = a;
    }
    __syncthreads();

    if (j < 64) {
        float a = bh1[j];
        for (int k = 0; k < HH; k++) a += zz[k] * Wh1[k * 64 + j];
        h1s[j] = fmaxf(a, 0.f);
    }
    __syncthreads();

    if (j == 0) {
        float a = bh2[0];
        for (int k = 0; k < 64; k++) a += h1s[k] * Wh2[k];
        out[0] = 1.0f / (1.0f + expf(-a));
    }
}

// ---------------- host ----------------
extern "C" void kernel_launch(void* const* d_in, const int* in_sizes, int n_in,
                              void* d_out, int out_size) {
    const float* xs  = (const float*)d_in[0];
    const int*   ei  = (const int*)d_in[1];
    const float* Wl1 = (const float*)d_in[2];
    const float* Wr1 = (const float*)d_in[3];
    const float* b1  = (const float*)d_in[4];
    const float* Wl2 = (const float*)d_in[5];
    const float* Wr2 = (const float*)d_in[6];
    const float* b2  = (const float*)d_in[7];
    const float* Wl3 = (const float*)d_in[8];
    const float* Wr3 = (const float*)d_in[9];
    const float* b3  = (const float*)d_in[10];
    const float* Wq  = (const float*)d_in[11];
    const float* bq  = (const float*)d_in[12];
    const float* Wk  = (const float*)d_in[13];
    const float* bk  = (const float*)d_in[14];
    const float* Wv  = (const float*)d_in[15];
    const float* bv  = (const float*)d_in[16];
    const float* Wo  = (const float*)d_in[17];
    const float* bo  = (const float*)d_in[18];
    const float* Wh1 = (const float*)d_in[19];
    const float* bh1 = (const float*)d_in[20];
    const float* Wh2 = (const float*)d_in[21];
    const float* bh2 = (const float*)d_in[22];
    float* out = (float*)d_out;

    float *agg, *bufA, *bufB, *inv, *pooled;
    int *cnt, *off, *cur, *csr, *bsum, *bbase;
    cudaGetSymbolAddress((void**)&agg,    g_agg);
    cudaGetSymbolAddress((void**)&bufA,   g_bufA);
    cudaGetSymbolAddress((void**)&bufB,   g_bufB);
    cudaGetSymbolAddress((void**)&inv,    g_inv);
    cudaGetSymbolAddress((void**)&pooled, g_pooled);
    cudaGetSymbolAddress((void**)&cnt,    g_cnt);
    cudaGetSymbolAddress((void**)&off,    g_off);
    cudaGetSymbolAddress((void**)&cur,    g_cur);
    cudaGetSymbolAddress((void**)&csr,    g_csr);
    cudaGetSymbolAddress((void**)&bsum,   g_bsum);
    cudaGetSymbolAddress((void**)&bbase,  g_bbase);

    const int aggBlocks  = (NN * 32 + 255) / 256;
    const int gemmBlocks = (NN + 127) / 128;

    zero_f4_kernel<<<1, 256>>>((float4*)pooled, TT * HH / 4);

    for (int t = 0; t < TT; t++) {
        const float* x_t = xs + (size_t)t * NN * FF;
        const int* src_t = ei + (size_t)t * 2 * EE;
        const int* dst_t = src_t + EE;

        // ---- CSR build (shared across 3 layers) ----
        zero_i_kernel<<<(NN + 255) / 256, 256>>>(cnt, NN);
        deg_kernel<<<(EE + 255) / 256, 256>>>(dst_t, cnt, EE);
        scan_reduce_kernel<<<SCAN_BLOCKS, 256>>>(cnt, bsum);
        scan_top_kernel<<<1, 256>>>(bsum, bbase, off + NN);
        scan_final_kernel<<<SCAN_BLOCKS, 256>>>(cnt, bbase, off, cur, inv);
        fill_kernel<<<(EE + 255) / 256, 256>>>(src_t, dst_t, cur, csr, EE);

        // ---- layer 1 ----
        agg_kernel<<<aggBlocks, 256>>>(x_t, off, csr, inv, agg);
        sage_gemm_kernel<false><<<gemmBlocks, 256>>>(agg, x_t, Wl1, Wr1, b1, bufA, NN);

        // ---- layer 2 ----
        agg_kernel<<<aggBlocks, 256>>>(bufA, off, csr, inv, agg);
        sage_gemm_kernel<false><<<gemmBlocks, 256>>>(agg, bufA, Wl2, Wr2, b2, bufB, NN);

        // ---- layer 3 (feeds mean-pool only) ----
        agg_kernel<<<aggBlocks, 256>>>(bufB, off, csr, inv, agg);
        sage_gemm_kernel<true><<<gemmBlocks, 256>>>(agg, bufB, Wl3, Wr3, b3,
                                                    pooled + t * HH, NN);
    }

    head_kernel<<<1, 128>>>(pooled, Wq, bq, Wk, bk, Wv, bv, Wo, bo, Wh1, bh1, Wh2, bh2, out);
}

// round 10
// speedup vs baseline: 1.7639x; 1.0814x over previous
#include <cuda_runtime.h>
#include <cuda_bf16.h>
#include <stdint.h>
#include <math.h>

#define TT 8
#define NN 50000
#define EE 800000
#define FF 128
#define HH 128
#define SCAN_BLOCKS ((NN + 255) / 256)   // 196

// ---------------- device scratch (no allocs allowed) ----------------
__device__ float g_agg[(size_t)NN * HH];
__device__ float g_bufA[(size_t)NN * HH];
__device__ float g_bufB[(size_t)NN * HH];
__device__ int   g_cnt[NN];
__device__ int   g_off[NN + 1];
__device__ int   g_cur[NN];
__device__ int   g_csr[EE];
__device__ int   g_bsum[SCAN_BLOCKS];
__device__ int   g_bbase[SCAN_BLOCKS];
__device__ float g_inv[NN];
__device__ float g_pooled[TT * HH];

// ---------------- packed f32x2 helpers ----------------
__device__ __forceinline__ unsigned long long pack_dup(float a) {
    unsigned long long r;
    unsigned int au = __float_as_uint(a);
    asm("mov.b64 %0, {%1, %1};" : "=l"(r) : "r"(au));
    return r;
}
__device__ __forceinline__ void ffma2(unsigned long long& acc, unsigned long long a,
                                      unsigned long long b) {
    asm("fma.rn.f32x2 %0, %1, %2, %3;" : "=l"(acc) : "l"(a), "l"(b), "l"(acc));
}
__device__ __forceinline__ void unpack2(unsigned long long v, float& lo, float& hi) {
    unsigned int l, h;
    asm("mov.b64 {%0, %1}, %2;" : "=r"(l), "=r"(h) : "l"(v));
    lo = __uint_as_float(l);
    hi = __uint_as_float(h);
}

// ---------------- small utility kernels ----------------
__global__ void zero_i_kernel(int* __restrict__ p, int n) {
    int i = blockIdx.x * blockDim.x + threadIdx.x;
    if (i < n) p[i] = 0;
}
__global__ void zero_f4_kernel(float4* __restrict__ p, int n4) {
    int i = blockIdx.x * blockDim.x + threadIdx.x;
    if (i < n4) p[i] = make_float4(0.f, 0.f, 0.f, 0.f);
}
__global__ void deg_kernel(const int* __restrict__ dst, int* __restrict__ cnt, int E) {
    int e = blockIdx.x * blockDim.x + threadIdx.x;
    if (e < E) atomicAdd(&cnt[dst[e]], 1);
}

// ---------------- 3-stage scan over cnt ----------------
__global__ void scan_reduce_kernel(const int* __restrict__ cnt, int* __restrict__ bsum) {
    __shared__ int wsum[8];
    int i = blockIdx.x * 256 + threadIdx.x;
    int v = (i < NN) ? cnt[i] : 0;
    int lane = threadIdx.x & 31, wid = threadIdx.x >> 5;
    int s = v;
#pragma unroll
    for (int o = 16; o > 0; o >>= 1) s += __shfl_down_sync(0xffffffffu, s, o);
    if (lane == 0) wsum[wid] = s;
    __syncthreads();
    if (threadIdx.x == 0) {
        int t = 0;
#pragma unroll
        for (int w = 0; w < 8; w++) t += wsum[w];
        bsum[blockIdx.x] = t;
    }
}

__global__ void scan_top_kernel(const int* __restrict__ bsum, int* __restrict__ bbase,
                                int* __restrict__ off_last) {
    __shared__ int wsum[8];
    int tid = threadIdx.x;
    int v = (tid < SCAN_BLOCKS) ? bsum[tid] : 0;
    int lane = tid & 31, wid = tid >> 5;
    int s = v;
#pragma unroll
    for (int o = 1; o < 32; o <<= 1) {
        int t = __shfl_up_sync(0xffffffffu, s, o);
        if (lane >= o) s += t;
    }
    if (lane == 31) wsum[wid] = s;
    __syncthreads();
    if (wid == 0) {
        int ws = (lane < 8) ? wsum[lane] : 0;
#pragma unroll
        for (int o = 1; o < 8; o <<= 1) {
            int t = __shfl_up_sync(0xffffffffu, ws, o);
            if (lane >= o) ws += t;
        }
        if (lane < 8) wsum[lane] = ws;
    }
    __syncthreads();
    int incl = s + (wid > 0 ? wsum[wid - 1] : 0);
    if (tid < SCAN_BLOCKS) bbase[tid] = incl - v;
    if (tid == 255) off_last[0] = incl;
}

__global__ void scan_final_kernel(const int* __restrict__ cnt, const int* __restrict__ bbase,
                                  int* __restrict__ off, int* __restrict__ cur,
                                  float* __restrict__ inv) {
    __shared__ int wsum[8];
    int i = blockIdx.x * 256 + threadIdx.x;
    int v = (i < NN) ? cnt[i] : 0;
    int lane = threadIdx.x & 31, wid = threadIdx.x >> 5;
    int s = v;
#pragma unroll
    for (int o = 1; o < 32; o <<= 1) {
        int t = __shfl_up_sync(0xffffffffu, s, o);
        if (lane >= o) s += t;
    }
    if (lane == 31) wsum[wid] = s;
    __syncthreads();
    if (wid == 0) {
        int ws = (lane < 8) ? wsum[lane] : 0;
#pragma unroll
        for (int o = 1; o < 8; o <<= 1) {
            int t = __shfl_up_sync(0xffffffffu, ws, o);
            if (lane >= o) ws += t;
        }
        if (lane < 8) wsum[lane] = ws;
    }
    __syncthreads();
    int excl = s - v + (wid > 0 ? wsum[wid - 1] : 0) + bbase[blockIdx.x];
    if (i < NN) {
        off[i] = excl;
        cur[i] = excl;
        inv[i] = 1.0f / (float)(v > 0 ? v : 1);
    }
}

__global__ void fill_kernel(const int* __restrict__ src, const int* __restrict__ dst,
                            int* __restrict__ cur, int* __restrict__ csr, int E) {
    int e = blockIdx.x * blockDim.x + threadIdx.x;
    if (e < E) {
        int d = dst[e];
        int p = atomicAdd(&cur[d], 1);
        csr[p] = src[e];
    }
}

// ---------------- pull-side aggregation: one warp per dst node --------------
__global__ __launch_bounds__(256)
void agg_kernel(const float* __restrict__ x,
                const int* __restrict__ off,
                const int* __restrict__ csr,
                const float* __restrict__ inv,
                float* __restrict__ agg) {
    int node = (blockIdx.x * blockDim.x + threadIdx.x) >> 5;
    if (node >= NN) return;
    int lane = threadIdx.x & 31;
    int e = off[node];
    int e1 = off[node + 1];
    float4 acc = make_float4(0.f, 0.f, 0.f, 0.f);
    for (; e + 1 < e1; e += 2) {
        int s0 = csr[e];
        int s1 = csr[e + 1];
        float4 v0 = ((const float4*)(x + (size_t)s0 * HH))[lane];
        float4 v1 = ((const float4*)(x + (size_t)s1 * HH))[lane];
        acc.x += v0.x + v1.x;
        acc.y += v0.y + v1.y;
        acc.z += v0.z + v1.z;
        acc.w += v0.w + v1.w;
    }
    if (e < e1) {
        int s0 = csr[e];
        float4 v0 = ((const float4*)(x + (size_t)s0 * HH))[lane];
        acc.x += v0.x; acc.y += v0.y; acc.z += v0.z; acc.w += v0.w;
    }
    float sc = inv[node];
    acc.x *= sc; acc.y *= sc; acc.z *= sc; acc.w *= sc;
    ((float4*)(agg + (size_t)node * HH))[lane] = acc;
}

// ---------------- fused SAGE GEMM: FFMA2 + ping-pong smem double buffer ----------
// out = relu(aggS @ Wl + x @ Wr + b); tile 128x128, K=256, BK=16, 256 threads.
template<bool POOL>
__global__ __launch_bounds__(256, 2)
void sage_gemm_kernel(const float* __restrict__ A1,   // agg (scaled), K 0..127
                      const float* __restrict__ A2,   // x,            K 128..255
                      const float* __restrict__ Wl,
                      const float* __restrict__ Wr,
                      const float* __restrict__ bias,
                      float* __restrict__ out,
                      int n) {
    __shared__ float As[2][16][128];
    __shared__ float Bs[2][16][128];

    int tid = threadIdx.x;
    int tx = tid & 15;        // col group (8 cols = 4 f32x2)
    int ty = tid >> 4;        // row group (8 rows)
    int row0 = blockIdx.x * 128;

    // load roles
    int li = tid >> 2;          // A row 0..63 (+64)
    int lk = (tid & 3) * 4;     // A k sub 0,4,8,12
    int bk = tid >> 5;          // B k 0..7 (+8)
    int bj = (tid & 31) * 4;    // B col

    unsigned long long acc2[8][4];
#pragma unroll
    for (int r = 0; r < 8; r++)
#pragma unroll
        for (int c = 0; c < 4; c++) acc2[r][c] = 0ull;

    float4 rA0, rA1, rB0, rB1;

#define GLOAD(kt) do { \
        int k0 = (kt) * 16; \
        const float* Asrc = (k0 < 128) ? A1 : A2; \
        const float* Wsrc = (k0 < 128) ? Wl : Wr; \
        int ksrc = (k0 < 128) ? k0 : (k0 - 128); \
        int gi0 = row0 + li; \
        int gi1 = gi0 + 64; \
        rA0 = make_float4(0.f, 0.f, 0.f, 0.f); \
        rA1 = make_float4(0.f, 0.f, 0.f, 0.f); \
        if (gi0 < n) rA0 = *(const float4*)&Asrc[(size_t)gi0 * 128 + ksrc + lk]; \
        if (gi1 < n) rA1 = *(const float4*)&Asrc[(size_t)gi1 * 128 + ksrc + lk]; \
        rB0 = *(const float4*)&Wsrc[(size_t)(ksrc + bk) * 128 + bj]; \
        rB1 = *(const float4*)&Wsrc[(size_t)(ksrc + bk + 8) * 128 + bj]; \
    } while (0)

#define SSTORE(kt) do { \
        int b = (kt) & 1; \
        As[b][lk + 0][li] = rA0.x; As[b][lk + 1][li] = rA0.y; \
        As[b][lk + 2][li] = rA0.z; As[b][lk + 3][li] = rA0.w; \
        As[b][lk + 0][li + 64] = rA1.x; As[b][lk + 1][li + 64] = rA1.y; \
        As[b][lk + 2][li + 64] = rA1.z; As[b][lk + 3][li + 64] = rA1.w; \
        *(float4*)&Bs[b][bk][bj] = rB0; \
        *(float4*)&Bs[b][bk + 8][bj] = rB1; \
    } while (0)

    GLOAD(0);
    SSTORE(0);

#pragma unroll 1
    for (int kt = 0; kt < 16; kt++) {
        if (kt < 15) GLOAD(kt + 1);          // LDG for next tile (latency covered)
        __syncthreads();                     // current tile's STS visible
        int b = kt & 1;
#pragma unroll
        for (int k = 0; k < 16; k++) {
            float a[8];
            *(float4*)&a[0] = *(const float4*)&As[b][k][ty * 8];
            *(float4*)&a[4] = *(const float4*)&As[b][k][ty * 8 + 4];
            unsigned long long b2[4];
            const unsigned long long* bp = (const unsigned long long*)&Bs[b][k][tx * 8];
            b2[0] = bp[0]; b2[1] = bp[1]; b2[2] = bp[2]; b2[3] = bp[3];
#pragma unroll
            for (int r = 0; r < 8; r++) {
                unsigned long long aa = pack_dup(a[r]);
                ffma2(acc2[r][0], aa, b2[0]);
                ffma2(acc2[r][1], aa, b2[1]);
                ffma2(acc2[r][2], aa, b2[2]);
                ffma2(acc2[r][3], aa, b2[3]);
            }
        }
        if (kt < 15) SSTORE(kt + 1);         // other buffer; safe w/o extra sync
    }
    __syncthreads();

    float bv[8];
    *(float4*)&bv[0] = *(const float4*)&bias[tx * 8];
    *(float4*)&bv[4] = *(const float4*)&bias[tx * 8 + 4];

    if (!POOL) {
#pragma unroll
        for (int r = 0; r < 8; r++) {
            int gi = row0 + ty * 8 + r;
            if (gi < n) {
                float o[8];
#pragma unroll
                for (int c = 0; c < 4; c++) {
                    float lo, hi;
                    unpack2(acc2[r][c], lo, hi);
                    o[2 * c]     = fmaxf(lo + bv[2 * c], 0.f);
                    o[2 * c + 1] = fmaxf(hi + bv[2 * c + 1], 0.f);
                }
                *(float4*)&out[(size_t)gi * 128 + tx * 8]     = *(float4*)&o[0];
                *(float4*)&out[(size_t)gi * 128 + tx * 8 + 4] = *(float4*)&o[4];
            }
        }
    } else {
        float colsum[8];
#pragma unroll
        for (int c = 0; c < 8; c++) colsum[c] = 0.f;
#pragma unroll
        for (int r = 0; r < 8; r++) {
            int gi = row0 + ty * 8 + r;
            if (gi < n) {
#pragma unroll
                for (int c = 0; c < 4; c++) {
                    float lo, hi;
                    unpack2(acc2[r][c], lo, hi);
                    colsum[2 * c]     += fmaxf(lo + bv[2 * c], 0.f);
                    colsum[2 * c + 1] += fmaxf(hi + bv[2 * c + 1], 0.f);
                }
            }
        }
        float* red = &As[0][0][0];
        *(float4*)&red[ty * 128 + tx * 8]     = *(float4*)&colsum[0];
        *(float4*)&red[ty * 128 + tx * 8 + 4] = *(float4*)&colsum[4];
        __syncthreads();
        if (ty == 0) {
#pragma unroll
            for (int c = 0; c < 8; c++) {
                float s = 0.f;
#pragma unroll
                for (int g = 0; g < 16; g++) s += red[g * 128 + tx * 8 + c];
                atomicAdd(&out[tx * 8 + c], s);
            }
        }
    }
#undef GLOAD
#undef SSTORE
}

// ---------------- head: attention (only last q row) + MLP + sigmoid ----------------
__global__ void head_kernel(const float* __restrict__ pooled,
                            const float* __restrict__ Wq, const float* __restrict__ bq,
                            const float* __restrict__ Wk, const float* __restrict__ bk,
                            const float* __restrict__ Wv, const float* __restrict__ bv,
                            const float* __restrict__ Wo, const float* __restrict__ bo,
                            const float* __restrict__ Wh1, const float* __restrict__ bh1,
                            const float* __restrict__ Wh2, const float* __restrict__ bh2,
                            float* __restrict__ out) {
    __shared__ float seq[TT][HH];
    __shared__ float kk_s[TT][HH];
    __shared__ float vv_s[TT][HH];
    __shared__ float qv[HH];
    __shared__ float sc[4][TT];
    __shared__ float ol[HH];
    __shared__ float zz[HH];
    __shared__ float h1s[64];

    int j = threadIdx.x;  // 0..127
    const float invN = 1.0f / (float)NN;

    for (int t = 0; t < TT; t++) seq[t][j] = pooled[t * HH + j] * invN;
    __syncthreads();

    {
        float aq = bq[j];
        for (int k = 0; k < HH; k++) aq += seq[TT - 1][k] * Wq[k * HH + j];
        qv[j] = aq;
        for (int t = 0; t < TT; t++) {
            float ak = bk[j], av = bv[j];
            for (int k = 0; k < HH; k++) {
                float s = seq[t][k];
                ak += s * Wk[k * HH + j];
                av += s * Wv[k * HH + j];
            }
            kk_s[t][j] = ak;
            vv_s[t][j] = av;
        }
    }
    __syncthreads();

    if (j < 32) {
        int h = j >> 3, t = j & 7;
        float s = 0.f;
        for (int d = 0; d < 32; d++) s += qv[h * 32 + d] * kk_s[t][h * 32 + d];
        sc[h][t] = s * 0.17677669529663687f;
    }
    __syncthreads();
    if (j < 4) {
        float m = sc[j][0];
        for (int t = 1; t < TT; t++) m = fmaxf(m, sc[j][t]);
        float s = 0.f;
        for (int t = 0; t < TT; t++) { float e = expf(sc[j][t] - m); sc[j][t] = e; s += e; }
        float r = 1.0f / s;
        for (int t = 0; t < TT; t++) sc[j][t] *= r;
    }
    __syncthreads();

    {
        int h = j >> 5;
        float o = 0.f;
        for (int t = 0; t < TT; t++) o += sc[h][t] * vv_s[t][j];
        ol[j] = o;
    }
    __syncthreads();

    {
        float a = bo[j];
        for (int k = 0; k < HH; k++) a += ol[k] * Wo[k * HH + j];
        zz[j] = a;
    }
    __syncthreads();

    if (j < 64) {
        float a = bh1[j];
        for (int k = 0; k < HH; k++) a += zz[k] * Wh1[k * 64 + j];
        h1s[j] = fmaxf(a, 0.f);
    }
    __syncthreads();

    if (j == 0) {
        float a = bh2[0];
        for (int k = 0; k < 64; k++) a += h1s[k] * Wh2[k];
        out[0] = 1.0f / (1.0f + expf(-a));
    }
}

// ---------------- host ----------------
extern "C" void kernel_launch(void* const* d_in, const int* in_sizes, int n_in,
                              void* d_out, int out_size) {
    const float* xs  = (const float*)d_in[0];
    const int*   ei  = (const int*)d_in[1];
    const float* Wl1 = (const float*)d_in[2];
    const float* Wr1 = (const float*)d_in[3];
    const float* b1  = (const float*)d_in[4];
    const float* Wl2 = (const float*)d_in[5];
    const float* Wr2 = (const float*)d_in[6];
    const float* b2  = (const float*)d_in[7];
    const float* Wl3 = (const float*)d_in[8];
    const float* Wr3 = (const float*)d_in[9];
    const float* b3  = (const float*)d_in[10];
    const float* Wq  = (const float*)d_in[11];
    const float* bq  = (const float*)d_in[12];
    const float* Wk  = (const float*)d_in[13];
    const float* bk  = (const float*)d_in[14];
    const float* Wv  = (const float*)d_in[15];
    const float* bv  = (const float*)d_in[16];
    const float* Wo  = (const float*)d_in[17];
    const float* bo  = (const float*)d_in[18];
    const float* Wh1 = (const float*)d_in[19];
    const float* bh1 = (const float*)d_in[20];
    const float* Wh2 = (const float*)d_in[21];
    const float* bh2 = (const float*)d_in[22];
    float* out = (float*)d_out;

    float *agg, *bufA, *bufB, *inv, *pooled;
    int *cnt, *off, *cur, *csr, *bsum, *bbase;
    cudaGetSymbolAddress((void**)&agg,    g_agg);
    cudaGetSymbolAddress((void**)&bufA,   g_bufA);
    cudaGetSymbolAddress((void**)&bufB,   g_bufB);
    cudaGetSymbolAddress((void**)&inv,    g_inv);
    cudaGetSymbolAddress((void**)&pooled, g_pooled);
    cudaGetSymbolAddress((void**)&cnt,    g_cnt);
    cudaGetSymbolAddress((void**)&off,    g_off);
    cudaGetSymbolAddress((void**)&cur,    g_cur);
    cudaGetSymbolAddress((void**)&csr,    g_csr);
    cudaGetSymbolAddress((void**)&bsum,   g_bsum);
    cudaGetSymbolAddress((void**)&bbase,  g_bbase);

    const int aggBlocks  = (NN * 32 + 255) / 256;
    const int gemmBlocks = (NN + 127) / 128;

    zero_f4_kernel<<<1, 256>>>((float4*)pooled, TT * HH / 4);

    for (int t = 0; t < TT; t++) {
        const float* x_t = xs + (size_t)t * NN * FF;
        const int* src_t = ei + (size_t)t * 2 * EE;
        const int* dst_t = src_t + EE;

        // ---- CSR build (shared across 3 layers) ----
        zero_i_kernel<<<(NN + 255) / 256, 256>>>(cnt, NN);
        deg_kernel<<<(EE + 255) / 256, 256>>>(dst_t, cnt, EE);
        scan_reduce_kernel<<<SCAN_BLOCKS, 256>>>(cnt, bsum);
        scan_top_kernel<<<1, 256>>>(bsum, bbase, off + NN);
        scan_final_kernel<<<SCAN_BLOCKS, 256>>>(cnt, bbase, off, cur, inv);
        fill_kernel<<<(EE + 255) / 256, 256>>>(src_t, dst_t, cur, csr, EE);

        // ---- layer 1 ----
        agg_kernel<<<aggBlocks, 256>>>(x_t, off, csr, inv, agg);
        sage_gemm_kernel<false><<<gemmBlocks, 256>>>(agg, x_t, Wl1, Wr1, b1, bufA, NN);

        // ---- layer 2 ----
        agg_kernel<<<aggBlocks, 256>>>(bufA, off, csr, inv, agg);
        sage_gemm_kernel<false><<<gemmBlocks, 256>>>(agg, bufA, Wl2, Wr2, b2, bufB, NN);

        // ---- layer 3 (feeds mean-pool only) ----
        agg_kernel<<<aggBlocks, 256>>>(bufB, off, csr, inv, agg);
        sage_gemm_kernel<true><<<gemmBlocks, 256>>>(agg, bufB, Wl3, Wr3, b3,
                                                    pooled + t * HH, NN);
    }

    head_kernel<<<1, 128>>>(pooled, Wq, bq, Wk, bk, Wv, bv, Wo, bo, Wh1, bh1, Wh2, bh2, out);
}